// round 4
// baseline (speedup 1.0000x reference)
#include <cuda_runtime.h>
#include <math.h>

#define H_DIM   4096
#define BATCH   64
#define T_STEPS 128
#define I_DIM   1024
#define NNZ_IH  131072
#define NNZ_HH  262144
#define NNZ_ALL (NNZ_IH + NNZ_HH)

#define NBLK    18          // row-blocks (equal-entry partition)
#define NTHR    256
#define NBINS   1024
#define ELLCAP  (1 << 21)   // 2M padded entries (16MB) — ample

// ---------------- scratch (device globals; no runtime allocation) ----------------
__device__ float g_xT[T_STEPS * 8 * I_DIM * 8];   // x as [t][bg][i][8 lanes]
__device__ float g_h[2][8 * H_DIM * 8];           // h images [bg][r][8 lanes]
__device__ int   g_rowLen[H_DIM];
__device__ int   g_lenBin[NBINS];
__device__ int   g_binOff[NBINS];
__device__ int   g_binCnt[NBINS];
__device__ int   g_rank[H_DIM];      // row -> sorted pos
__device__ int   g_sorted[H_DIM];    // sorted pos -> row
__device__ int   g_slen[H_DIM];      // sorted lengths
__device__ int   g_spre[H_DIM];      // exclusive prefix of sorted lengths
__device__ int   g_posBlk[H_DIM];    // sorted pos -> block id
__device__ int   g_blkStart[NBLK + 1];
__device__ int   g_blkRpb[NBLK];
__device__ int   g_blkLen[NBLK];     // max len in block (= last row's len)
__device__ int   g_ellOff[NBLK];
__device__ int   g_rowFill[H_DIM];
__device__ int2  g_ell[ELLCAP];      // (col', val); col' = col (hh) or 4096+col (ih)
__device__ float g_biasPerm[H_DIM];

// ---------------- setup kernels ----------------
__global__ void k_zero0() {
    int idx = blockIdx.x * blockDim.x + threadIdx.x;
    if (idx < 8 * H_DIM * 8) g_h[0][idx] = 0.0f;
    if (idx < H_DIM) { g_rowLen[idx] = 0; g_rowFill[idx] = 0; }
    if (idx < NBINS) { g_lenBin[idx] = 0; g_binCnt[idx] = 0; }
}

__global__ void k_len(const int* __restrict__ ih_rows, const int* __restrict__ hh_rows) {
    int k = blockIdx.x * blockDim.x + threadIdx.x;
    if (k < NNZ_IH) atomicAdd(&g_rowLen[ih_rows[k]], 1);
    if (k < NNZ_HH) atomicAdd(&g_rowLen[hh_rows[k]], 1);
}

__global__ void k_lenhist() {
    int r = blockIdx.x * blockDim.x + threadIdx.x;
    if (r < H_DIM) {
        int l = g_rowLen[r];
        if (l > NBINS - 1) l = NBINS - 1;
        atomicAdd(&g_lenBin[l], 1);
    }
}

// exclusive scan of 1024 length bins (one block)
__global__ void k_binscan() {
    __shared__ int sums[NBINS];
    int tid = threadIdx.x;
    int v = g_lenBin[tid];
    sums[tid] = v;
    __syncthreads();
    for (int off = 1; off < NBINS; off <<= 1) {
        int t = (tid >= off) ? sums[tid - off] : 0;
        __syncthreads();
        sums[tid] += t;
        __syncthreads();
    }
    g_binOff[tid] = sums[tid] - v;
}

__global__ void k_rank() {
    int r = blockIdx.x * blockDim.x + threadIdx.x;
    if (r < H_DIM) {
        int len = g_rowLen[r];
        int b = (len > NBINS - 1) ? NBINS - 1 : len;
        int pos = g_binOff[b] + atomicAdd(&g_binCnt[b], 1);
        g_rank[r] = pos;
        g_sorted[pos] = r;
    }
}

__global__ void k_slen() {
    int pos = blockIdx.x * blockDim.x + threadIdx.x;
    if (pos < H_DIM) g_slen[pos] = g_rowLen[g_sorted[pos]];
}

// exclusive prefix of 4096 sorted lengths (one block, 4 per thread)
__global__ void k_scan4096() {
    __shared__ int sums[1024];
    int tid  = threadIdx.x;
    int base = tid * 4;
    int v0 = g_slen[base + 0];
    int v1 = g_slen[base + 1];
    int v2 = g_slen[base + 2];
    int v3 = g_slen[base + 3];
    int local = v0 + v1 + v2 + v3;
    sums[tid] = local;
    __syncthreads();
    for (int off = 1; off < 1024; off <<= 1) {
        int t = (tid >= off) ? sums[tid - off] : 0;
        __syncthreads();
        sums[tid] += t;
        __syncthreads();
    }
    int excl = sums[tid] - local;
    g_spre[base + 0] = excl;
    g_spre[base + 1] = excl + v0;
    g_spre[base + 2] = excl + v0 + v1;
    g_spre[base + 3] = excl + v0 + v1 + v2;
}

// equal-work block boundaries from the prefix sum
__global__ void k_bounds() {
    int pos = blockIdx.x * blockDim.x + threadIdx.x;
    if (pos < H_DIM) {
        const long long S = NNZ_ALL;
        int b = (int)((long long)g_spre[pos] * NBLK / S);
        if (b > NBLK - 1) b = NBLK - 1;
        g_posBlk[pos] = b;
        int bprev = -1;
        if (pos > 0) {
            bprev = (int)((long long)g_spre[pos - 1] * NBLK / S);
            if (bprev > NBLK - 1) bprev = NBLK - 1;
        }
        for (int k = bprev + 1; k <= b; k++) g_blkStart[k] = pos;
        if (pos == H_DIM - 1) g_blkStart[NBLK] = H_DIM;
    }
}

__global__ void k_blkmeta() {
    int run = 0;
    for (int b = 0; b < NBLK; b++) {
        int rpb = g_blkStart[b + 1] - g_blkStart[b];
        int lm  = g_slen[g_blkStart[b + 1] - 1];   // ascending sort -> max is last
        g_blkRpb[b] = rpb;
        g_blkLen[b] = lm;
        g_ellOff[b] = run;
        run += rpb * lm;
    }
}

__global__ void k_zeroell() {
    int idx = blockIdx.x * blockDim.x + threadIdx.x;
    if (idx < ELLCAP) g_ell[idx] = make_int2(0, 0);
}

__global__ void k_fill(const int* __restrict__ ih_rows, const int* __restrict__ ih_cols,
                       const float* __restrict__ ih_vals,
                       const int* __restrict__ hh_rows, const int* __restrict__ hh_cols,
                       const float* __restrict__ hh_vals) {
    int k = blockIdx.x * blockDim.x + threadIdx.x;
    if (k < NNZ_IH) {
        int r = ih_rows[k];
        int pos = g_rank[r];
        int b = g_posBlk[pos];
        int j = atomicAdd(&g_rowFill[pos], 1);
        g_ell[g_ellOff[b] + j * g_blkRpb[b] + (pos - g_blkStart[b])] =
            make_int2(ih_cols[k] + H_DIM, __float_as_int(ih_vals[k]));
    }
    if (k < NNZ_HH) {
        int r = hh_rows[k];
        int pos = g_rank[r];
        int b = g_posBlk[pos];
        int j = atomicAdd(&g_rowFill[pos], 1);
        g_ell[g_ellOff[b] + j * g_blkRpb[b] + (pos - g_blkStart[b])] =
            make_int2(hh_cols[k], __float_as_int(hh_vals[k]));
    }
}

__global__ void k_biasperm(const float* __restrict__ bias) {
    int pos = blockIdx.x * blockDim.x + threadIdx.x;
    if (pos < H_DIM) g_biasPerm[pos] = bias[g_sorted[pos]];
}

// x (B,T,I) -> g_xT [t][bg][i][8]
__global__ void k_transpose_x(const float* __restrict__ x) {
    __shared__ float tile[32][33];
    int t  = blockIdx.z;
    int i0 = blockIdx.x * 32;
    int b0 = blockIdx.y * 32;
    int b = b0 + threadIdx.y;
    int i = i0 + threadIdx.x;
    tile[threadIdx.y][threadIdx.x] = x[((size_t)b * T_STEPS + t) * I_DIM + i];
    __syncthreads();
    int iw = i0 + threadIdx.y;
    int bw = b0 + threadIdx.x;
    g_xT[(((size_t)t * 8 + (bw >> 3)) * I_DIM + iw) * 8 + (bw & 7)] =
        tile[threadIdx.x][threadIdx.y];
}

// ---------------- per-timestep kernel ----------------
// grid (NBLK, 8). smem: h rows 0..4095 at sm[col*8], x at sm[(4096+i)*8] (160KB).
__global__ void __launch_bounds__(NTHR, 1)
k_step(float* __restrict__ out, int t, int prev) {
    extern __shared__ float sm[];
    int b   = blockIdx.x;
    int bg  = blockIdx.y;
    int tid = threadIdx.x;

    // fill h slice; b==0 blocks also emit out[t-1] from the same registers
    const float4* __restrict__ hsrc = (const float4*)(g_h[prev] + (size_t)bg * H_DIM * 8);
    float4* hdst = (float4*)sm;
    if (b == 0 && t > 0) {
        const size_t bstride = (size_t)T_STEPS * H_DIM;
        #pragma unroll 4
        for (int i = tid; i < H_DIM * 2; i += NTHR) {
            float4 v = hsrc[i];
            hdst[i] = v;
            int r = i >> 1;
            int b0 = bg * 8 + ((i & 1) << 2);
            size_t o = (size_t)b0 * bstride + (size_t)(t - 1) * H_DIM + r;
            out[o] = v.x;
            out[o + bstride] = v.y;
            out[o + 2 * bstride] = v.z;
            out[o + 3 * bstride] = v.w;
        }
    } else {
        #pragma unroll 8
        for (int i = tid; i < H_DIM * 2; i += NTHR) hdst[i] = hsrc[i];
    }

    const float4* __restrict__ xsrc =
        (const float4*)(g_xT + (((size_t)t * 8 + bg) * I_DIM) * 8);
    float4* xdst = (float4*)(sm + H_DIM * 8);
    #pragma unroll 8
    for (int i = tid; i < I_DIM * 2; i += NTHR) xdst[i] = xsrc[i];

    int start = g_blkStart[b];
    int rpb   = g_blkRpb[b];
    int len   = g_blkLen[b];
    const int2* __restrict__ ellbase = g_ell + g_ellOff[b];
    __syncthreads();

    for (int s = tid; s < rpb; s += NTHR) {
        int pos = start + s;
        float bv = g_biasPerm[pos];
        float a0 = bv, a1 = bv, a2 = bv, a3 = bv;
        float a4 = bv, a5 = bv, a6 = bv, a7 = bv;

        const int2* __restrict__ ell = ellbase + s;
        #pragma unroll 4
        for (int j = 0; j < len; j++) {
            int2 w = ell[(size_t)j * rpb];
            float v = __int_as_float(w.y);
            const float4* hp = (const float4*)(sm + w.x * 8);
            float4 A = hp[0], B = hp[1];
            a0 += v * A.x; a1 += v * A.y; a2 += v * A.z; a3 += v * A.w;
            a4 += v * B.x; a5 += v * B.y; a6 += v * B.z; a7 += v * B.w;
        }

        float4 h0 = make_float4(tanhf(a0), tanhf(a1), tanhf(a2), tanhf(a3));
        float4 h1 = make_float4(tanhf(a4), tanhf(a5), tanhf(a6), tanhf(a7));

        int r_true = g_sorted[pos];
        float4* hw = (float4*)(g_h[prev ^ 1] + ((size_t)bg * H_DIM + r_true) * 8);
        hw[0] = h0;
        hw[1] = h1;
    }
}

// emit out[:, 127, :] from the final h image (g_h[0] after 128 steps)
__global__ void k_flush(float* __restrict__ out) {
    int bg  = blockIdx.x;
    int tid = threadIdx.x;
    const size_t bstride = (size_t)T_STEPS * H_DIM;
    for (int it = 0; it < H_DIM / NTHR; it++) {
        int r = it * NTHR + tid;
        const float4* p = (const float4*)(g_h[0] + ((size_t)bg * H_DIM + r) * 8);
        float4 A = p[0], B = p[1];
        size_t o = (size_t)(bg * 8) * bstride + (size_t)127 * H_DIM + r;
        out[o] = A.x;               out[o + bstride] = A.y;
        out[o + 2 * bstride] = A.z; out[o + 3 * bstride] = A.w;
        out[o + 4 * bstride] = B.x; out[o + 5 * bstride] = B.y;
        out[o + 6 * bstride] = B.z; out[o + 7 * bstride] = B.w;
    }
}

// ---------------- launch ----------------
extern "C" void kernel_launch(void* const* d_in, const int* in_sizes, int n_in,
                              void* d_out, int out_size) {
    const float* x       = (const float*)d_in[0];
    const float* ih_vals = (const float*)d_in[1];
    const float* hh_vals = (const float*)d_in[2];
    const float* hh_bias = (const float*)d_in[3];
    const int*   ih_rows = (const int*)  d_in[4];
    const int*   ih_cols = (const int*)  d_in[5];
    const int*   hh_rows = (const int*)  d_in[6];
    const int*   hh_cols = (const int*)  d_in[7];
    float* out = (float*)d_out;

    static int smem_set = 0;
    const int SMEM_BYTES = (H_DIM + I_DIM) * 8 * (int)sizeof(float);  // 160KB
    if (!smem_set) {
        cudaFuncSetAttribute(k_step, cudaFuncAttributeMaxDynamicSharedMemorySize,
                             SMEM_BYTES);
        smem_set = 1;
    }

    // ---- setup: lengths -> sort -> equal-work partition -> ELL -> x rearrange ----
    k_zero0<<<(8 * H_DIM * 8 + 255) / 256, 256>>>();
    k_len<<<(NNZ_HH + 255) / 256, 256>>>(ih_rows, hh_rows);
    k_lenhist<<<(H_DIM + 255) / 256, 256>>>();
    k_binscan<<<1, NBINS>>>();
    k_rank<<<(H_DIM + 255) / 256, 256>>>();
    k_slen<<<(H_DIM + 255) / 256, 256>>>();
    k_scan4096<<<1, 1024>>>();
    k_bounds<<<(H_DIM + 255) / 256, 256>>>();
    k_blkmeta<<<1, 1>>>();
    k_zeroell<<<(ELLCAP + 255) / 256, 256>>>();
    k_fill<<<(NNZ_HH + 255) / 256, 256>>>(ih_rows, ih_cols, ih_vals,
                                          hh_rows, hh_cols, hh_vals);
    k_biasperm<<<(H_DIM + 255) / 256, 256>>>(hh_bias);
    k_transpose_x<<<dim3(I_DIM / 32, BATCH / 32, T_STEPS), dim3(32, 32)>>>(x);

    // ---- sequential RNN steps ----
    for (int t = 0; t < T_STEPS; t++) {
        k_step<<<dim3(NBLK, 8), NTHR, SMEM_BYTES>>>(out, t, t & 1);
    }
    k_flush<<<8, NTHR>>>(out);
}

// round 5
// speedup vs baseline: 1.8156x; 1.8156x over previous
#include <cuda_runtime.h>
#include <cuda_fp16.h>
#include <math.h>

#define H_DIM   4096
#define BATCH   64
#define T_STEPS 128
#define I_DIM   1024
#define NNZ_IH  131072
#define NNZ_HH  262144

#define ROWS_PER_BLK 8      // warps per block; 1 warp = 1 row, 64 batch via half2

// ---------------- scratch (device globals; no runtime allocation) ----------------
__device__ __half g_x16[(size_t)T_STEPS * I_DIM * BATCH];  // x as (T, I, B) fp16, 16MB
__device__ __half g_h16[2][H_DIM * BATCH];                 // h ping-pong (H, B) fp16
__device__ int    g_ih_ptr[H_DIM + 1];
__device__ int    g_hh_ptr[H_DIM + 1];
__device__ int2   g_ih_pk[NNZ_IH];     // (col, val fp32 bits)
__device__ int2   g_hh_pk[NNZ_HH];
__device__ int    g_cnt[2 * H_DIM];

// ---------------- setup kernels ----------------
__global__ void k_zero_all() {
    int idx = blockIdx.x * blockDim.x + threadIdx.x;
    if (idx < H_DIM * BATCH) g_h16[0][idx] = __float2half(0.0f);
    if (idx < 2 * H_DIM)     g_cnt[idx]   = 0;
}

__global__ void k_zero_cnt() {
    int idx = blockIdx.x * blockDim.x + threadIdx.x;
    if (idx < 2 * H_DIM) g_cnt[idx] = 0;
}

__global__ void k_hist(const int* __restrict__ ih_rows, const int* __restrict__ hh_rows) {
    int k = blockIdx.x * blockDim.x + threadIdx.x;
    if (k < NNZ_IH) atomicAdd(&g_cnt[ih_rows[k]], 1);
    if (k < NNZ_HH) atomicAdd(&g_cnt[H_DIM + hh_rows[k]], 1);
}

// exclusive scan of 4096 counts -> row pointers (one block per matrix)
__global__ void k_scan() {
    __shared__ int sums[1024];
    int which = blockIdx.x;              // 0 = ih, 1 = hh
    int* cnt = &g_cnt[which * H_DIM];
    int* ptr = which ? g_hh_ptr : g_ih_ptr;
    int tid  = threadIdx.x;
    int base = tid * 4;
    int v0 = cnt[base + 0];
    int v1 = cnt[base + 1];
    int v2 = cnt[base + 2];
    int v3 = cnt[base + 3];
    int local = v0 + v1 + v2 + v3;
    sums[tid] = local;
    __syncthreads();
    for (int off = 1; off < 1024; off <<= 1) {
        int t = (tid >= off) ? sums[tid - off] : 0;
        __syncthreads();
        sums[tid] += t;
        __syncthreads();
    }
    int excl = sums[tid] - local;
    ptr[base + 0] = excl;
    ptr[base + 1] = excl + v0;
    ptr[base + 2] = excl + v0 + v1;
    ptr[base + 3] = excl + v0 + v1 + v2;
    if (tid == 1023) ptr[H_DIM] = sums[1023];
}

__global__ void k_scatter(const int* __restrict__ ih_rows, const int* __restrict__ ih_cols,
                          const float* __restrict__ ih_vals,
                          const int* __restrict__ hh_rows, const int* __restrict__ hh_cols,
                          const float* __restrict__ hh_vals) {
    int k = blockIdx.x * blockDim.x + threadIdx.x;
    if (k < NNZ_IH) {
        int r = ih_rows[k];
        int p = g_ih_ptr[r] + atomicAdd(&g_cnt[r], 1);
        g_ih_pk[p] = make_int2(ih_cols[k], __float_as_int(ih_vals[k]));
    }
    if (k < NNZ_HH) {
        int r = hh_rows[k];
        int p = g_hh_ptr[r] + atomicAdd(&g_cnt[H_DIM + r], 1);
        g_hh_pk[p] = make_int2(hh_cols[k], __float_as_int(hh_vals[k]));
    }
}

// x (B,T,I) fp32 -> g_x16 (T,I,B) fp16
__global__ void k_transpose_x(const float* __restrict__ x) {
    __shared__ float tile[32][33];
    int t  = blockIdx.z;
    int i0 = blockIdx.x * 32;
    int b0 = blockIdx.y * 32;
    int b = b0 + threadIdx.y;
    int i = i0 + threadIdx.x;
    tile[threadIdx.y][threadIdx.x] = x[((size_t)b * T_STEPS + t) * I_DIM + i];
    __syncthreads();
    int iw = i0 + threadIdx.y;
    int bw = b0 + threadIdx.x;
    g_x16[((size_t)t * I_DIM + iw) * BATCH + bw] =
        __float2half(tile[threadIdx.x][threadIdx.y]);
}

// ---------------- per-timestep kernel ----------------
// block (32, ROWS_PER_BLK): warp = 1 row; lane l = batch pair (2l, 2l+1).
// Every gather is one coalesced 128B line (64 fp16).
__global__ void __launch_bounds__(32 * ROWS_PER_BLK)
k_step(const float* __restrict__ bias, float* __restrict__ out, int t, int prev) {
    int lane = threadIdx.x;
    int ty   = threadIdx.y;
    int r    = blockIdx.x * ROWS_PER_BLK + ty;

    const __half2* __restrict__ hb = (const __half2*)g_h16[prev];
    const __half2* __restrict__ xb =
        (const __half2*)(g_x16 + (size_t)t * I_DIM * BATCH);

    float bv = bias[r];
    float ax = bv, ay = bv;

    int k0 = g_ih_ptr[r];
    int k1 = g_ih_ptr[r + 1];
    #pragma unroll 4
    for (int k = k0; k < k1; k++) {
        int2 w = g_ih_pk[k];
        float v = __int_as_float(w.y);
        float2 f = __half22float2(xb[w.x * (BATCH / 2) + lane]);
        ax += v * f.x;
        ay += v * f.y;
    }

    k0 = g_hh_ptr[r];
    k1 = g_hh_ptr[r + 1];
    #pragma unroll 4
    for (int k = k0; k < k1; k++) {
        int2 w = g_hh_pk[k];
        float v = __int_as_float(w.y);
        float2 f = __half22float2(hb[w.x * (BATCH / 2) + lane]);
        ax += v * f.x;
        ay += v * f.y;
    }

    float hx = tanhf(ax);
    float hy = tanhf(ay);

    // h_next fp16: warp writes one 128B line
    ((__half2*)g_h16[prev ^ 1])[r * (BATCH / 2) + lane] =
        __floats2half2_rn(hx, hy);

    // out (B,T,H) fp32 via smem transpose for coalesced stores
    __shared__ float tile[ROWS_PER_BLK][BATCH + 1];
    tile[ty][2 * lane]     = hx;
    tile[ty][2 * lane + 1] = hy;
    __syncthreads();
    int idx = ty * 32 + lane;                       // 0..255
    #pragma unroll
    for (int s = 0; s < 2; s++) {
        int id = idx + s * (32 * ROWS_PER_BLK);     // 0..511
        int b  = id >> 3;                           // 0..63
        int rr = id & 7;                            // 0..7
        out[((size_t)b * T_STEPS + t) * H_DIM + blockIdx.x * ROWS_PER_BLK + rr] =
            tile[rr][b];
    }
}

// ---------------- launch ----------------
extern "C" void kernel_launch(void* const* d_in, const int* in_sizes, int n_in,
                              void* d_out, int out_size) {
    const float* x       = (const float*)d_in[0];
    const float* ih_vals = (const float*)d_in[1];
    const float* hh_vals = (const float*)d_in[2];
    const float* hh_bias = (const float*)d_in[3];
    const int*   ih_rows = (const int*)  d_in[4];
    const int*   ih_cols = (const int*)  d_in[5];
    const int*   hh_rows = (const int*)  d_in[6];
    const int*   hh_cols = (const int*)  d_in[7];
    float* out = (float*)d_out;

    // CSR build + x transpose/convert (graph-capturable, deterministic)
    k_zero_all<<<(H_DIM * BATCH + 255) / 256, 256>>>();
    k_hist<<<(NNZ_HH + 255) / 256, 256>>>(ih_rows, hh_rows);
    k_scan<<<2, 1024>>>();
    k_zero_cnt<<<(2 * H_DIM + 255) / 256, 256>>>();
    k_scatter<<<(NNZ_HH + 255) / 256, 256>>>(ih_rows, ih_cols, ih_vals,
                                             hh_rows, hh_cols, hh_vals);
    k_transpose_x<<<dim3(I_DIM / 32, BATCH / 32, T_STEPS), dim3(32, 32)>>>(x);

    // sequential RNN steps
    for (int t = 0; t < T_STEPS; t++) {
        k_step<<<H_DIM / ROWS_PER_BLK, dim3(32, ROWS_PER_BLK)>>>(
            hh_bias, out, t, t & 1);
    }
}